// round 11
// baseline (speedup 1.0000x reference)
#include <cuda_runtime.h>
#include <cuda_fp16.h>
#include <math.h>
#include <stdint.h>

#define D      128
#define MAXN   8192
#define BM     128
#define PITCHB 272              // smem tile pitch bytes (136 halves)
#define TILEB  (128 * PITCHB)   // 34816
#define PT     129              // dist tile pitch (floats)
#define PACK   16777216.0       // 2^24 for (ps, ct) double packing

__device__ __half  g_h[(size_t)MAXN * D];
__device__ float   g_sqh[MAXN];
__device__ float   g_negdist[MAXN];
__device__ double  g_acc[MAXN];
__device__ float   g_part[64];

// ---------------- helpers ----------------
__device__ __forceinline__ uint32_t smem_u32(const void* p) {
    uint32_t a;
    asm("{ .reg .u64 t; cvta.to.shared.u64 t, %1; cvt.u32.u64 %0, t; }"
        : "=r"(a) : "l"(p));
    return a;
}
__device__ __forceinline__ void cp_async16(uint32_t dst, const void* src) {
    size_t g = __cvta_generic_to_global(src);
    asm volatile("cp.async.cg.shared.global [%0], [%1], 16;"
                 :: "r"(dst), "l"(g) : "memory");
}
__device__ __forceinline__ void ldm_x4(uint32_t* r, uint32_t addr) {
    asm volatile("ldmatrix.sync.aligned.m8n8.x4.shared.b16 {%0,%1,%2,%3}, [%4];"
                 : "=r"(r[0]), "=r"(r[1]), "=r"(r[2]), "=r"(r[3]) : "r"(addr));
}
__device__ __forceinline__ void mma_f16(float* c, const uint32_t* a,
                                        uint32_t b0, uint32_t b1) {
    asm volatile(
        "mma.sync.aligned.m16n8k16.row.col.f32.f16.f16.f32 "
        "{%0,%1,%2,%3}, {%4,%5,%6,%7}, {%8,%9}, {%0,%1,%2,%3};"
        : "+f"(c[0]), "+f"(c[1]), "+f"(c[2]), "+f"(c[3])
        : "r"(a[0]), "r"(a[1]), "r"(a[2]), "r"(a[3]), "r"(b0), "r"(b1));
}

// ---------------------------------------------------------------------------
// Kernel 1: warp-per-row normalize; fp16 rows, sq of ROUNDED rows, neg_dist,
// zero accumulator (fused — no separate k_zero launch).
// ---------------------------------------------------------------------------
__global__ __launch_bounds__(256) void k_normalize(const float* __restrict__ pred,
                                                   const float* __restrict__ neg,
                                                   int N) {
    int w = threadIdx.x >> 5, lane = threadIdx.x & 31;
    int row = blockIdx.x * 8 + w;
    float4 pv = ((const float4*)pred)[(size_t)row * 32 + lane];
    float4 nv = ((const float4*)neg)[(size_t)row * 32 + lane];
    float s1 = pv.x * pv.x + pv.y * pv.y + pv.z * pv.z + pv.w * pv.w;
    float s2 = nv.x * nv.x + nv.y * nv.y + nv.z * nv.z + nv.w * nv.w;
    #pragma unroll
    for (int o = 16; o > 0; o >>= 1) {
        s1 += __shfl_xor_sync(0xffffffffu, s1, o);
        s2 += __shfl_xor_sync(0xffffffffu, s2, o);
    }
    float r1 = fmaxf(sqrtf(s1), 1e-12f);
    float r2 = fmaxf(sqrtf(s2), 1e-12f);
    float4 pn = make_float4(pv.x / r1, pv.y / r1, pv.z / r1, pv.w / r1);
    float4 nn = make_float4(nv.x / r2, nv.y / r2, nv.z / r2, nv.w / r2);

    __half h0 = __float2half(pn.x), h1 = __float2half(pn.y);
    __half h2 = __float2half(pn.z), h3 = __float2half(pn.w);
    float f0 = __half2float(h0), f1 = __half2float(h1);
    float f2 = __half2float(h2), f3 = __half2float(h3);
    float s3 = f0 * f0 + f1 * f1 + f2 * f2 + f3 * f3;   // sq of rounded
    float dx = pn.x - nn.x, dy = pn.y - nn.y, dz = pn.z - nn.z, dw = pn.w - nn.w;
    float s4 = dx * dx + dy * dy + dz * dz + dw * dw;
    #pragma unroll
    for (int o = 16; o > 0; o >>= 1) {
        s3 += __shfl_xor_sync(0xffffffffu, s3, o);
        s4 += __shfl_xor_sync(0xffffffffu, s4, o);
    }
    __half2* dst = (__half2*)(g_h + (size_t)row * D) + lane * 2;
    dst[0] = __halves2half2(h0, h1);
    dst[1] = __halves2half2(h2, h3);
    if (lane == 0) {
        g_sqh[row]     = s3;
        g_negdist[row] = (s4 > 0.f) ? sqrtf(s4) : 0.f;
        g_acc[row]     = 0.0;
    }
}

// ---------------------------------------------------------------------------
// Kernel 2: 128x128 gram tiles. Off-diagonal tiles first (0..noff-1),
// diagonal tiles LAST (cheap tail wave). Single fp16 mma pass, occ 2.
// ---------------------------------------------------------------------------
#define OFF_SQI (2 * TILEB)
#define OFF_SQJ (2 * TILEB + 512)
#define SMEM_SZ (2 * TILEB + 1024)

__global__ __launch_bounds__(256, 2) void k_gram(const float* __restrict__ mask,
                                                 int N, int nb, int noff) {
    int bi, bj;
    bool diag;
    int t = blockIdx.x;
    if (t >= noff) {               // diagonal tiles, scheduled last
        bi = bj = t - noff;
        diag = true;
    } else {                       // strict upper triangle: rows have nb-1-bi
        float ff = (float)(2 * nb - 1);
        bi = (int)((ff - sqrtf(ff * ff - 8.0f * (float)t)) * 0.5f);
        #pragma unroll 1
        while (bi > 0 && (bi * nb - (bi * (bi + 1)) / 2) > t) bi--;
        #pragma unroll 1
        while (((bi + 1) * nb - ((bi + 1) * (bi + 2)) / 2) <= t) bi++;
        bj = bi + 1 + (t - (bi * nb - (bi * (bi + 1)) / 2));
        diag = false;
    }
    int I = bi * BM, J = bj * BM;

    extern __shared__ char smem[];
    uint32_t sbase = smem_u32(smem);
    float* sdist = (float*)smem;
    float* sqi = (float*)(smem + OFF_SQI);
    float* sqj = (float*)(smem + OFF_SQJ);

    int tid = threadIdx.x, wid = tid >> 5, lane = tid & 31;
    int wr = wid >> 1, wc = wid & 1;   // warp tile: rows wr*32, cols wc*64

    // stage both fp16 tiles via cp.async
    {
        const char* srcA = (const char*)(g_h + (size_t)I * D);
        const char* srcB = (const char*)(g_h + (size_t)J * D);
        #pragma unroll
        for (int t2 = tid; t2 < 2048; t2 += 256) {
            int r = t2 >> 4, c = t2 & 15;
            cp_async16(sbase + (uint32_t)(r * PITCHB + c * 16),
                       srcA + (size_t)r * 256 + c * 16);
            cp_async16(sbase + TILEB + (uint32_t)(r * PITCHB + c * 16),
                       srcB + (size_t)r * 256 + c * 16);
        }
        asm volatile("cp.async.commit_group;" ::: "memory");
    }
    if (tid < 128) sqi[tid] = g_sqh[I + tid];
    else sqj[tid - 128] = g_sqh[J + tid - 128];
    asm volatile("cp.async.wait_group 0;" ::: "memory");
    __syncthreads();

    float acc[2][8][4];
    #pragma unroll
    for (int mi = 0; mi < 2; mi++)
        #pragma unroll
        for (int ni = 0; ni < 8; ni++)
            #pragma unroll
            for (int q = 0; q < 4; q++) acc[mi][ni][q] = 0.f;

    uint32_t aAddr0 = sbase + (uint32_t)((wr * 32 + (lane & 15)) * PITCHB +
                                         (lane >> 4) * 16);
    uint32_t bAddr0 = sbase + TILEB +
                      (uint32_t)((wc * 64 + (lane & 15)) * PITCHB +
                                 (lane >> 4) * 16);

    #pragma unroll
    for (int ks = 0; ks < 8; ks++) {
        uint32_t a[2][4];
        ldm_x4(a[0], aAddr0 + ks * 32);
        ldm_x4(a[1], aAddr0 + ks * 32 + 16 * PITCHB);
        uint32_t b[4][4];
        #pragma unroll
        for (int n2 = 0; n2 < 4; n2++)
            ldm_x4(b[n2], bAddr0 + ks * 32 + n2 * 16 * PITCHB);
        #pragma unroll
        for (int mi = 0; mi < 2; mi++)
            #pragma unroll
            for (int ni = 0; ni < 8; ni++)
                mma_f16(acc[mi][ni], a[mi],
                        b[ni >> 1][ni & 1], b[ni >> 1][(ni & 1) + 2]);
    }
    __syncthreads();   // operands dead; reuse smem for dist tile

    // dot -> dist via guarded rsqrt
    #pragma unroll
    for (int mi = 0; mi < 2; mi++) {
        int rbase = wr * 32 + mi * 16 + (lane >> 2);
        #pragma unroll
        for (int ni = 0; ni < 8; ni++) {
            int cbase = wc * 64 + ni * 8 + (lane & 3) * 2;
            #pragma unroll
            for (int q = 0; q < 4; q++) {
                int r = rbase + (q >> 1) * 8;
                int c = cbase + (q & 1);
                float d2 = sqi[r] + sqj[c] - 2.f * acc[mi][ni][q];
                float dv = (d2 > 0.f) ? d2 * __frsqrt_rn(d2) : 0.f;
                if (diag && r == c) dv = 0.f;
                sdist[r * PT + c] = dv;
            }
        }
    }
    __syncthreads();

    // fused epilogue: one A-row (+ one B-row off-diag) per iteration
    #pragma unroll 4
    for (int rr = 0; rr < 16; rr++) {
        int r = wid * 16 + rr;
        // pass A: vector load, cols 4*lane..4*lane+3
        float4 mA = ((const float4*)(mask + (size_t)(I + r) * N + J))[lane];
        const float* drow = sdist + r * PT + lane * 4;
        float psA = mA.x * drow[0] + mA.y * drow[1] +
                    mA.z * drow[2] + mA.w * drow[3];
        float ctA = mA.x + mA.y + mA.z + mA.w;
        float psB = 0.f, ctB = 0.f;
        if (!diag) {
            const float* mrowB = mask + (size_t)(J + r) * N + I;
            float mB[4];
            #pragma unroll
            for (int q = 0; q < 4; q++) mB[q] = mrowB[q * 32 + lane];
            #pragma unroll
            for (int q = 0; q < 4; q++) {
                psB += mB[q] * sdist[(q * 32 + lane) * PT + r];
                ctB += mB[q];
            }
        }
        #pragma unroll
        for (int o = 16; o > 0; o >>= 1) {
            psA += __shfl_down_sync(0xffffffffu, psA, o);
            ctA += __shfl_down_sync(0xffffffffu, ctA, o);
            psB += __shfl_down_sync(0xffffffffu, psB, o);
            ctB += __shfl_down_sync(0xffffffffu, ctB, o);
        }
        if (lane == 0) {
            atomicAdd(&g_acc[I + r], (double)psA + (double)ctA * PACK);
            if (!diag)
                atomicAdd(&g_acc[J + r], (double)psB + (double)ctB * PACK);
        }
    }
}

// ---------------------------------------------------------------------------
// Kernel 3a: parallel unpack + per-block partial sums
// ---------------------------------------------------------------------------
__global__ __launch_bounds__(256) void k_final1(int N) {
    __shared__ float sb[8];
    int i = blockIdx.x * 256 + threadIdx.x;
    float s = 0.f;
    if (i < N) {
        double v = g_acc[i];
        double ct = floor(v * (1.0 / PACK));
        float ps = (float)(v - ct * PACK);
        float c  = (float)ct;
        s = ps / fmaxf(c, 1.f) - g_negdist[i];
    }
    #pragma unroll
    for (int o = 16; o > 0; o >>= 1) s += __shfl_down_sync(0xffffffffu, s, o);
    int lane = threadIdx.x & 31, w = threadIdx.x >> 5;
    if (lane == 0) sb[w] = s;
    __syncthreads();
    if (w == 0) {
        float r = (lane < 8) ? sb[lane] : 0.f;
        #pragma unroll
        for (int o = 4; o > 0; o >>= 1) r += __shfl_down_sync(0xffffffffu, r, o);
        if (lane == 0) g_part[blockIdx.x] = r;
    }
}

// ---------------------------------------------------------------------------
// Kernel 3b: sum partials -> scalar mean
// ---------------------------------------------------------------------------
__global__ void k_final2(float* __restrict__ out, int N, int nparts) {
    float s = (threadIdx.x < nparts) ? g_part[threadIdx.x] : 0.f;
    #pragma unroll
    for (int o = 16; o > 0; o >>= 1) s += __shfl_down_sync(0xffffffffu, s, o);
    if (threadIdx.x == 0) out[0] = s / (float)N;
}

// ---------------------------------------------------------------------------
extern "C" void kernel_launch(void* const* d_in, const int* in_sizes, int n_in,
                              void* d_out, int out_size) {
    const float* pred = (const float*)d_in[0];
    const float* mask = (const float*)d_in[1];
    const float* neg  = (const float*)d_in[2];
    int N = in_sizes[0] / D;

    k_normalize<<<N / 8, 256>>>(pred, neg, N);

    int nb = N / BM;
    int noff = nb * (nb - 1) / 2;          // strict upper-triangle tiles
    int ntiles = noff + nb;                // + diagonal tiles (last)
    cudaFuncSetAttribute(k_gram, cudaFuncAttributeMaxDynamicSharedMemorySize,
                         SMEM_SZ);
    k_gram<<<ntiles, 256, SMEM_SZ>>>(mask, N, nb, noff);

    int nparts = (N + 255) / 256;
    k_final1<<<nparts, 256>>>(N);
    k_final2<<<1, 32>>>((float*)d_out, N, nparts);
}

// round 12
// speedup vs baseline: 1.0696x; 1.0696x over previous
#include <cuda_runtime.h>
#include <cuda_fp16.h>
#include <math.h>
#include <stdint.h>

#define D      128
#define MAXN   8192
#define BM     128
#define PITCHB 272              // smem tile pitch bytes (136 halves)
#define TILEB  (128 * PITCHB)   // 34816
#define PT     129              // dist tile pitch (floats)
#define PACK   16777216.0       // 2^24 for (ps, ct) double packing
#define SLOTS  5                // mask ring slots per warp (1KB each)
#define DEPTH  4                // cp.async pipeline depth

__device__ __half  g_h[(size_t)MAXN * D];
__device__ float   g_sqh[MAXN];
__device__ float   g_negdist[MAXN];
__device__ double  g_acc[MAXN];
__device__ float   g_part[64];

// ---------------- helpers ----------------
__device__ __forceinline__ uint32_t smem_u32(const void* p) {
    uint32_t a;
    asm("{ .reg .u64 t; cvta.to.shared.u64 t, %1; cvt.u32.u64 %0, t; }"
        : "=r"(a) : "l"(p));
    return a;
}
__device__ __forceinline__ void cp_async16(uint32_t dst, const void* src) {
    size_t g = __cvta_generic_to_global(src);
    asm volatile("cp.async.cg.shared.global [%0], [%1], 16;"
                 :: "r"(dst), "l"(g) : "memory");
}
__device__ __forceinline__ void ldm_x4(uint32_t* r, uint32_t addr) {
    asm volatile("ldmatrix.sync.aligned.m8n8.x4.shared.b16 {%0,%1,%2,%3}, [%4];"
                 : "=r"(r[0]), "=r"(r[1]), "=r"(r[2]), "=r"(r[3]) : "r"(addr));
}
__device__ __forceinline__ void mma_f16(float* c, const uint32_t* a,
                                        uint32_t b0, uint32_t b1) {
    asm volatile(
        "mma.sync.aligned.m16n8k16.row.col.f32.f16.f16.f32 "
        "{%0,%1,%2,%3}, {%4,%5,%6,%7}, {%8,%9}, {%0,%1,%2,%3};"
        : "+f"(c[0]), "+f"(c[1]), "+f"(c[2]), "+f"(c[3])
        : "r"(a[0]), "r"(a[1]), "r"(a[2]), "r"(a[3]), "r"(b0), "r"(b1));
}

// ---------------------------------------------------------------------------
// Kernel 1: warp-per-row normalize; fp16 rows, sq of ROUNDED rows, neg_dist,
// zero accumulator.
// ---------------------------------------------------------------------------
__global__ __launch_bounds__(256) void k_normalize(const float* __restrict__ pred,
                                                   const float* __restrict__ neg,
                                                   int N) {
    int w = threadIdx.x >> 5, lane = threadIdx.x & 31;
    int row = blockIdx.x * 8 + w;
    float4 pv = ((const float4*)pred)[(size_t)row * 32 + lane];
    float4 nv = ((const float4*)neg)[(size_t)row * 32 + lane];
    float s1 = pv.x * pv.x + pv.y * pv.y + pv.z * pv.z + pv.w * pv.w;
    float s2 = nv.x * nv.x + nv.y * nv.y + nv.z * nv.z + nv.w * nv.w;
    #pragma unroll
    for (int o = 16; o > 0; o >>= 1) {
        s1 += __shfl_xor_sync(0xffffffffu, s1, o);
        s2 += __shfl_xor_sync(0xffffffffu, s2, o);
    }
    float r1 = fmaxf(sqrtf(s1), 1e-12f);
    float r2 = fmaxf(sqrtf(s2), 1e-12f);
    float4 pn = make_float4(pv.x / r1, pv.y / r1, pv.z / r1, pv.w / r1);
    float4 nn = make_float4(nv.x / r2, nv.y / r2, nv.z / r2, nv.w / r2);

    __half h0 = __float2half(pn.x), h1 = __float2half(pn.y);
    __half h2 = __float2half(pn.z), h3 = __float2half(pn.w);
    float f0 = __half2float(h0), f1 = __half2float(h1);
    float f2 = __half2float(h2), f3 = __half2float(h3);
    float s3 = f0 * f0 + f1 * f1 + f2 * f2 + f3 * f3;   // sq of rounded
    float dx = pn.x - nn.x, dy = pn.y - nn.y, dz = pn.z - nn.z, dw = pn.w - nn.w;
    float s4 = dx * dx + dy * dy + dz * dz + dw * dw;
    #pragma unroll
    for (int o = 16; o > 0; o >>= 1) {
        s3 += __shfl_xor_sync(0xffffffffu, s3, o);
        s4 += __shfl_xor_sync(0xffffffffu, s4, o);
    }
    __half2* dst = (__half2*)(g_h + (size_t)row * D) + lane * 2;
    dst[0] = __halves2half2(h0, h1);
    dst[1] = __halves2half2(h2, h3);
    if (lane == 0) {
        g_sqh[row]     = s3;
        g_negdist[row] = (s4 > 0.f) ? sqrtf(s4) : 0.f;
        g_acc[row]     = 0.0;
    }
}

// ---------------------------------------------------------------------------
// Kernel 2: 128x128 gram tiles (upper triangle), single fp16 mma pass,
// warp-private cp.async mask pipeline overlapping DRAM with compute.
// ---------------------------------------------------------------------------
#define OFF_SQI (2 * TILEB)
#define OFF_SQJ (2 * TILEB + 512)
#define MB_OFF  (2 * TILEB + 1024)            // 70656
#define SMEM_SZ (MB_OFF + 8 * SLOTS * 1024)   // 111616

__global__ __launch_bounds__(256, 2) void k_gram(const float* __restrict__ mask,
                                                 int N, int nb) {
    // triangular decode: t -> (bi, bj), bj >= bi   (R9 layout)
    int t = blockIdx.x;
    float ff = (float)(2 * nb + 1);
    int bi = (int)((ff - sqrtf(ff * ff - 8.0f * (float)t)) * 0.5f);
    #pragma unroll 1
    while (bi > 0 && (bi * nb - (bi * (bi - 1)) / 2) > t) bi--;
    #pragma unroll 1
    while (((bi + 1) * nb - ((bi + 1) * bi) / 2) <= t) bi++;
    int bj = bi + (t - (bi * nb - (bi * (bi - 1)) / 2));
    bool diag = (bi == bj);
    int I = bi * BM, J = bj * BM;

    extern __shared__ char smem[];
    uint32_t sbase = smem_u32(smem);
    float* sdist = (float*)smem;
    float* sqi = (float*)(smem + OFF_SQI);
    float* sqj = (float*)(smem + OFF_SQJ);

    int tid = threadIdx.x, wid = tid >> 5, lane = tid & 31;
    int wr = wid >> 1, wc = wid & 1;   // warp tile: rows wr*32, cols wc*64
    uint32_t mbuf = sbase + MB_OFF + (uint32_t)wid * (SLOTS * 1024);

    // ---- group 0: stage both fp16 tiles via cp.async ----
    {
        const char* srcA = (const char*)(g_h + (size_t)I * D);
        const char* srcB = (const char*)(g_h + (size_t)J * D);
        #pragma unroll
        for (int t2 = tid; t2 < 2048; t2 += 256) {
            int r = t2 >> 4, c = t2 & 15;
            cp_async16(sbase + (uint32_t)(r * PITCHB + c * 16),
                       srcA + (size_t)r * 256 + c * 16);
            cp_async16(sbase + TILEB + (uint32_t)(r * PITCHB + c * 16),
                       srcB + (size_t)r * 256 + c * 16);
        }
        asm volatile("cp.async.commit_group;" ::: "memory");
    }

    // ---- groups 1..DEPTH: mask prologue (overlaps MMA below) ----
    #pragma unroll
    for (int k = 0; k < DEPTH; k++) {
        int r = wid * 16 + k;
        uint32_t dst = mbuf + (uint32_t)(k % SLOTS) * 1024;
        cp_async16(dst + lane * 16, mask + (size_t)(I + r) * N + J + lane * 4);
        if (!diag)
            cp_async16(dst + 512 + lane * 16,
                       mask + (size_t)(J + r) * N + I + lane * 4);
        asm volatile("cp.async.commit_group;" ::: "memory");
    }

    if (tid < 128) sqi[tid] = g_sqh[I + tid];
    else sqj[tid - 128] = g_sqh[J + tid - 128];
    // tiles (group 0) done when <= DEPTH groups pending
    asm volatile("cp.async.wait_group %0;" :: "n"(DEPTH) : "memory");
    __syncthreads();

    float acc[2][8][4];
    #pragma unroll
    for (int mi = 0; mi < 2; mi++)
        #pragma unroll
        for (int ni = 0; ni < 8; ni++)
            #pragma unroll
            for (int q = 0; q < 4; q++) acc[mi][ni][q] = 0.f;

    uint32_t aAddr0 = sbase + (uint32_t)((wr * 32 + (lane & 15)) * PITCHB +
                                         (lane >> 4) * 16);
    uint32_t bAddr0 = sbase + TILEB +
                      (uint32_t)((wc * 64 + (lane & 15)) * PITCHB +
                                 (lane >> 4) * 16);

    #pragma unroll
    for (int ks = 0; ks < 8; ks++) {
        uint32_t a[2][4];
        ldm_x4(a[0], aAddr0 + ks * 32);
        ldm_x4(a[1], aAddr0 + ks * 32 + 16 * PITCHB);
        uint32_t b[4][4];
        #pragma unroll
        for (int n2 = 0; n2 < 4; n2++)
            ldm_x4(b[n2], bAddr0 + ks * 32 + n2 * 16 * PITCHB);
        #pragma unroll
        for (int mi = 0; mi < 2; mi++)
            #pragma unroll
            for (int ni = 0; ni < 8; ni++)
                mma_f16(acc[mi][ni], a[mi],
                        b[ni >> 1][ni & 1], b[ni >> 1][(ni & 1) + 2]);
    }
    __syncthreads();   // operands dead; reuse tile region for dist tile

    // dot -> dist via guarded rsqrt
    #pragma unroll
    for (int mi = 0; mi < 2; mi++) {
        int rbase = wr * 32 + mi * 16 + (lane >> 2);
        #pragma unroll
        for (int ni = 0; ni < 8; ni++) {
            int cbase = wc * 64 + ni * 8 + (lane & 3) * 2;
            #pragma unroll
            for (int q = 0; q < 4; q++) {
                int r = rbase + (q >> 1) * 8;
                int c = cbase + (q & 1);
                float d2 = sqi[r] + sqj[c] - 2.f * acc[mi][ni][q];
                float dv = (d2 > 0.f) ? d2 * __frsqrt_rn(d2) : 0.f;
                if (diag && r == c) dv = 0.f;
                sdist[r * PT + c] = dv;
            }
        }
    }
    __syncthreads();

    // ---- pipelined epilogue: warp-private mask ring, zero barriers ----
    #pragma unroll 1
    for (int rr = 0; rr < 16; rr++) {
        // mask row rr complete when <= DEPTH-1 groups pending
        asm volatile("cp.async.wait_group %0;" :: "n"(DEPTH - 1) : "memory");
        __syncwarp();

        int r = wid * 16 + rr;
        const float* mbA = (const float*)(smem + MB_OFF +
                                          wid * (SLOTS * 1024) +
                                          (rr % SLOTS) * 1024);
        float4 mA = ((const float4*)mbA)[lane];
        const float* drow = sdist + r * PT + lane * 4;
        float psA = mA.x * drow[0] + mA.y * drow[1] +
                    mA.z * drow[2] + mA.w * drow[3];
        float ctA = mA.x + mA.y + mA.z + mA.w;

        float psB = 0.f, ctB = 0.f;
        if (!diag) {
            const float* mbB = mbA + 128;   // +512 bytes
            #pragma unroll
            for (int q = 0; q < 4; q++) {
                float m = mbB[q * 32 + lane];
                psB += m * sdist[(q * 32 + lane) * PT + r];
                ctB += m;
            }
        }
        #pragma unroll
        for (int o = 16; o > 0; o >>= 1) {
            psA += __shfl_down_sync(0xffffffffu, psA, o);
            ctA += __shfl_down_sync(0xffffffffu, ctA, o);
            psB += __shfl_down_sync(0xffffffffu, psB, o);
            ctB += __shfl_down_sync(0xffffffffu, ctB, o);
        }
        if (lane == 0) {
            atomicAdd(&g_acc[I + r], (double)psA + (double)ctA * PACK);
            if (!diag)
                atomicAdd(&g_acc[J + r], (double)psB + (double)ctB * PACK);
        }

        // issue row rr+DEPTH (or empty group to keep the count uniform)
        int rn = rr + DEPTH;
        if (rn < 16) {
            int r2 = wid * 16 + rn;
            uint32_t dst = mbuf + (uint32_t)(rn % SLOTS) * 1024;
            cp_async16(dst + lane * 16,
                       mask + (size_t)(I + r2) * N + J + lane * 4);
            if (!diag)
                cp_async16(dst + 512 + lane * 16,
                           mask + (size_t)(J + r2) * N + I + lane * 4);
        }
        asm volatile("cp.async.commit_group;" ::: "memory");
    }
}

// ---------------------------------------------------------------------------
// Kernel 3a: parallel unpack + per-block partial sums
// ---------------------------------------------------------------------------
__global__ __launch_bounds__(256) void k_final1(int N) {
    __shared__ float sb[8];
    int i = blockIdx.x * 256 + threadIdx.x;
    float s = 0.f;
    if (i < N) {
        double v = g_acc[i];
        double ct = floor(v * (1.0 / PACK));
        float ps = (float)(v - ct * PACK);
        float c  = (float)ct;
        s = ps / fmaxf(c, 1.f) - g_negdist[i];
    }
    #pragma unroll
    for (int o = 16; o > 0; o >>= 1) s += __shfl_down_sync(0xffffffffu, s, o);
    int lane = threadIdx.x & 31, w = threadIdx.x >> 5;
    if (lane == 0) sb[w] = s;
    __syncthreads();
    if (w == 0) {
        float r = (lane < 8) ? sb[lane] : 0.f;
        #pragma unroll
        for (int o = 4; o > 0; o >>= 1) r += __shfl_down_sync(0xffffffffu, r, o);
        if (lane == 0) g_part[blockIdx.x] = r;
    }
}

// ---------------------------------------------------------------------------
// Kernel 3b: sum partials -> scalar mean
// ---------------------------------------------------------------------------
__global__ void k_final2(float* __restrict__ out, int N, int nparts) {
    float s = (threadIdx.x < nparts) ? g_part[threadIdx.x] : 0.f;
    #pragma unroll
    for (int o = 16; o > 0; o >>= 1) s += __shfl_down_sync(0xffffffffu, s, o);
    if (threadIdx.x == 0) out[0] = s / (float)N;
}

// ---------------------------------------------------------------------------
extern "C" void kernel_launch(void* const* d_in, const int* in_sizes, int n_in,
                              void* d_out, int out_size) {
    const float* pred = (const float*)d_in[0];
    const float* mask = (const float*)d_in[1];
    const float* neg  = (const float*)d_in[2];
    int N = in_sizes[0] / D;

    k_normalize<<<N / 8, 256>>>(pred, neg, N);

    int nb = N / BM;
    int ntiles = nb * (nb + 1) / 2;
    cudaFuncSetAttribute(k_gram, cudaFuncAttributeMaxDynamicSharedMemorySize,
                         SMEM_SZ);
    k_gram<<<ntiles, 256, SMEM_SZ>>>(mask, N, nb);

    int nparts = (N + 255) / 256;
    k_final1<<<nparts, 256>>>(N);
    k_final2<<<1, 32>>>((float*)d_out, N, nparts);
}